// round 13
// baseline (speedup 1.0000x reference)
#include <cuda_runtime.h>
#include <math.h>

#define TT 512
#define BB 128
#define DD 128
#define HH 256
#define CC 10
#define G4 1024
#define MROWS (TT*BB)
#define NCTA 128
#define NGRP 16           // CTAs per barrier group = one batch-tile (16 nt CTAs)

// ---------------- static device scratch (no runtime allocation) ----------------
__device__ float g_e  [(size_t)MROWS * DD];
__device__ float g_XwF[(size_t)MROWS * G4];
__device__ float g_XwB[(size_t)MROWS * G4];
__device__ float g_seq[(size_t)MROWS * 2 * HH];
__device__ float g_state[4 * BB * HH];             // per dir: h parity buf0, buf1
__device__ unsigned g_bcount[8 * 32];
__device__ unsigned g_bepoch[8 * 32];

__device__ __forceinline__ void ffma2(float2 &d, float2 a, float2 b) {
    asm("fma.rn.f32x2 %0, %1, %2, %0;"
        : "+l"(*reinterpret_cast<unsigned long long*>(&d))
        : "l"(*reinterpret_cast<unsigned long long*>(&a)),
          "l"(*reinterpret_cast<unsigned long long*>(&b)));
}

__device__ __forceinline__ float sigf(float x) {
    return __fdividef(1.0f, 1.0f + __expf(-x));
}
__device__ __forceinline__ float tanhfast(float x) {
    return __fdividef(2.0f, 1.0f + __expf(-2.0f * x)) - 1.0f;
}

__device__ __forceinline__ void cpa16(unsigned dst, const void* src) {
    asm volatile("cp.async.cg.shared.global [%0], [%1], 16;" :: "r"(dst), "l"(src));
}
#define CPA_COMMIT() asm volatile("cp.async.commit_group;")
#define CPA_WAIT0()  asm volatile("cp.async.wait_group 0;")

__device__ __forceinline__ unsigned f2tf32(float x) {
    unsigned r; asm("cvt.rna.tf32.f32 %0, %1;" : "=r"(r) : "f"(x)); return r;
}
__device__ __forceinline__ void mma_tf32(float* c, const unsigned* a, const unsigned* b) {
    asm("mma.sync.aligned.m16n8k8.row.col.f32.tf32.tf32.f32 "
        "{%0,%1,%2,%3}, {%4,%5,%6,%7}, {%8,%9}, {%0,%1,%2,%3};"
        : "+f"(c[0]), "+f"(c[1]), "+f"(c[2]), "+f"(c[3])
        : "r"(a[0]), "r"(a[1]), "r"(a[2]), "r"(a[3]), "r"(b[0]), "r"(b[1]));
}

// per-group software barrier: 16 CTAs sharing one batch-tile
__device__ __forceinline__ void grid_bar(int grp, unsigned &epoch) {
    __threadfence();
    __syncthreads();
    if (threadIdx.x == 0) {
        unsigned* cnt = &g_bcount[grp * 32];
        unsigned* ep  = &g_bepoch[grp * 32];
        if (atomicAdd(cnt, 1) == NGRP - 1) {
            atomicExch(cnt, 0);
            __threadfence();
            atomicAdd(ep, 1);
        } else {
            while (*(volatile unsigned*)ep == epoch) { }
        }
        epoch++;
    }
    __syncthreads();
}

// ---------------- embedding gather ----------------
__global__ void embed_k(const int* __restrict__ x, const float* __restrict__ emb) {
    int gid = blockIdx.x * blockDim.x + threadIdx.x;
    int r  = gid >> 5;
    int c4 = gid & 31;
    int t  = r >> 7;
    int b  = r & 127;
    int tok = x[b * TT + t];
    reinterpret_cast<float4*>(g_e)[(size_t)r * 32 + c4] =
        reinterpret_cast<const float4*>(emb)[(size_t)tok * 32 + c4];
}

// ---------------- 3xTF32 tensor-core GEMM + bias (unchanged from R7) ----------------
#define AS_LD 20
#define BS_LD 136
__global__ __launch_bounds__(256) void gemm_k(int a_sel, int c_sel,
        const float* __restrict__ W, const float* __restrict__ bias, int K)
{
    const float* A = a_sel ? g_seq : g_e;
    float*       C = c_sel ? g_XwB : g_XwF;

    __shared__ __align__(16) float As[2][128][AS_LD];
    __shared__ __align__(16) float Bs[2][16][BS_LD];

    const int m0   = blockIdx.x * 128;
    const int n0   = blockIdx.y * 128;
    const int tid  = threadIdx.x;
    const int lane = tid & 31;
    const int warp = tid >> 5;
    const int gid  = lane >> 2;
    const int tig  = lane & 3;
    const int wm   = warp & 3;
    const int wn   = warp >> 2;

    const unsigned sA = (unsigned)__cvta_generic_to_shared(&As[0][0][0]);
    const unsigned sB = (unsigned)__cvta_generic_to_shared(&Bs[0][0][0]);
    const unsigned bufA = 128 * AS_LD * 4;
    const unsigned bufB = 16 * BS_LD * 4;

    float acc[2][8][4];
#pragma unroll
    for (int mb = 0; mb < 2; ++mb)
#pragma unroll
        for (int nb = 0; nb < 8; ++nb)
#pragma unroll
            for (int r = 0; r < 4; ++r) acc[mb][nb][r] = 0.f;

    const int nk = K >> 4;

    auto load_tile = [&](int buf, int kt) {
#pragma unroll
        for (int i = 0; i < 2; ++i) {
            int id = tid + i * 256;
            int r = id >> 2, kq = id & 3;
            cpa16(sA + buf * bufA + (unsigned)((r * AS_LD + kq * 4) * 4),
                  A + (size_t)(m0 + r) * K + kt + kq * 4);
        }
#pragma unroll
        for (int i = 0; i < 2; ++i) {
            int id = tid + i * 256;
            int r = id >> 5, c4 = (id & 31) * 4;
            cpa16(sB + buf * bufB + (unsigned)((r * BS_LD + c4) * 4),
                  W + (size_t)(kt + r) * G4 + n0 + c4);
        }
        CPA_COMMIT();
    };

    load_tile(0, 0);
    CPA_WAIT0();
    __syncthreads();

    for (int kt = 0; kt < nk; ++kt) {
        const int cur = kt & 1;
        const bool more = (kt + 1) < nk;
        if (more) load_tile(cur ^ 1, (kt + 1) << 4);

#pragma unroll
        for (int kh = 0; kh < 2; ++kh) {
            const int k0 = kh * 8;
            unsigned ahi[2][4], alo[2][4];
#pragma unroll
            for (int mb = 0; mb < 2; ++mb) {
                const int rbase = wm * 32 + mb * 16 + gid;
#pragma unroll
                for (int r = 0; r < 4; ++r) {
                    float v = As[cur][rbase + (r & 1) * 8][k0 + tig + (r >> 1) * 4];
                    unsigned h = f2tf32(v);
                    ahi[mb][r] = h;
                    alo[mb][r] = f2tf32(v - __uint_as_float(h));
                }
            }
#pragma unroll
            for (int nb = 0; nb < 8; ++nb) {
                const int nc = wn * 64 + nb * 8 + gid;
                float b0 = Bs[cur][k0 + tig][nc];
                float b1 = Bs[cur][k0 + tig + 4][nc];
                unsigned bh[2], bl[2];
                bh[0] = f2tf32(b0); bl[0] = f2tf32(b0 - __uint_as_float(bh[0]));
                bh[1] = f2tf32(b1); bl[1] = f2tf32(b1 - __uint_as_float(bh[1]));
#pragma unroll
                for (int mb = 0; mb < 2; ++mb) mma_tf32(acc[mb][nb], ahi[mb], bh);
#pragma unroll
                for (int mb = 0; mb < 2; ++mb) mma_tf32(acc[mb][nb], ahi[mb], bl);
#pragma unroll
                for (int mb = 0; mb < 2; ++mb) mma_tf32(acc[mb][nb], alo[mb], bh);
            }
        }
        if (more) {
            CPA_WAIT0();
            __syncthreads();
        }
    }

#pragma unroll
    for (int mb = 0; mb < 2; ++mb) {
        const int row0 = m0 + wm * 32 + mb * 16 + gid;
#pragma unroll
        for (int nb = 0; nb < 8; ++nb) {
            const int col = n0 + wn * 64 + nb * 8 + tig * 2;
            float2 bv = *reinterpret_cast<const float2*>(bias + col);
            float2 v0 = make_float2(acc[mb][nb][0] + bv.x, acc[mb][nb][1] + bv.y);
            float2 v1 = make_float2(acc[mb][nb][2] + bv.x, acc[mb][nb][3] + bv.y);
            *reinterpret_cast<float2*>(C + (size_t)row0 * G4 + col)       = v0;
            *reinterpret_cast<float2*>(C + (size_t)(row0 + 8) * G4 + col) = v1;
        }
    }
}

// ---------------- persistent bidirectional LSTM: dual-direction CTAs ----------------
// 128 CTAs (1/SM uniform): bid = bt*16 + nt16. Each CTA owns a 16-col slice for
// BOTH directions and advances fwd step s and bwd step s in the same k-loop:
// two independent dependency chains per warp -> ILP hides LDS/LDG latency without
// extra warps, no U smem duplication, and one barrier covers a step PAIR.
// Thread = 1 row x 2 cols x 4 gates x 2 dirs. U layout per dir (R12, 1-wf loads):
// Upk[d][k*16 + gp*8 + ng] = gate-pair float4 for cols (c, c+1), c = nt16*16 + ng*2.
__global__ __launch_bounds__(128) void lstm_persist_k(
        const float* __restrict__ Uf, const float* __restrict__ Ub, int write_seq)
{
    extern __shared__ float smp[];
    float4* Upk0 = reinterpret_cast<float4*>(smp);              // dir0: [256][16] f4
    float4* Upk1 = Upk0 + 4096;                                 // dir1
    float (*sh0)[260] = reinterpret_cast<float (*)[260]>(smp + 32768);       // h fwd
    float (*sh1)[260] = reinterpret_cast<float (*)[260]>(smp + 32768 + 16*260); // h bwd

    const int bid  = blockIdx.x;
    const int bt   = bid >> 4;
    const int nt16 = bid & 15;
    const int grp  = bt;
    const int tid  = threadIdx.x;

    // load both U slices (gate-pair blocked: gp*8+ng -> contiguous 128B per gp)
#pragma unroll
    for (int d = 0; d < 2; ++d) {
        const float* U = d ? Ub : Uf;
        float4* Upk = d ? Upk1 : Upk0;
        for (int i = tid; i < 4096; i += 128) {
            int k  = i >> 4;
            int f  = i & 15;
            int gp = f >> 3;
            int ng = f & 7;
            int col = nt16 * 16 + ng * 2;
            const float* src = U + (size_t)k * G4 + (2 * gp) * HH + col;
            float2 a = *reinterpret_cast<const float2*>(src);
            float2 b = *reinterpret_cast<const float2*>(src + HH);
            Upk[i] = make_float4(a.x, a.y, b.x, b.y);
        }
    }

    // zero my (bt, nt16) patch of both parity buffers, both dirs
    for (int i = tid; i < 256; i += 128) {
        int r  = bt * 16 + (i >> 4);
        int cc = nt16 * 16 + (i & 15);
#pragma unroll
        for (int d = 0; d < 2; ++d) {
            float* hb = g_state + (size_t)d * 2 * BB * HH;
            __stcg(hb + (size_t)r * HH + cc, 0.f);
            __stcg(hb + (size_t)BB * HH + (size_t)r * HH + cc, 0.f);
        }
    }

    unsigned epoch = 0;
    if (tid == 0) epoch = *(volatile unsigned*)&g_bepoch[grp * 32];
    grid_bar(grp, epoch);

    const int b16  = tid >> 3;          // row 0..15
    const int ng   = tid & 7;           // col pair 0..7
    const int nloc = ng * 2;
    const int ngl  = nt16 * 16 + nloc;
    const int r0   = bt * 16 + b16;

    float2 cst[2] = {make_float2(0.f, 0.f), make_float2(0.f, 0.f)};

    for (int s = 0; s < TT; ++s) {
        const int par = s & 1;
        const int tF  = s;
        const int tB  = TT - 1 - s;

        // stage h tiles for both dirs (16x256 each): 8 float4/thread/dir
#pragma unroll
        for (int i = 0; i < 8; ++i) {
            int f = tid + i * 128;
            int r = f >> 6, cq = f & 63;
            const float* hbF = g_state + (size_t)par * BB * HH;
            const float* hbB = g_state + 2 * BB * HH + (size_t)par * BB * HH;
            *reinterpret_cast<float4*>(&sh0[r][cq * 4]) =
                __ldcg(reinterpret_cast<const float4*>(
                    hbF + (size_t)(bt * 16 + r) * HH + cq * 4));
            *reinterpret_cast<float4*>(&sh1[r][cq * 4]) =
                __ldcg(reinterpret_cast<const float4*>(
                    hbB + (size_t)(bt * 16 + r) * HH + cq * 4));
        }
        // Xw seeds for both dirs (4 gates x 2 cols each)
        float2 acc0[4], acc1[4];
        {
            const float* xwF = g_XwF + ((size_t)tF * BB + r0) * G4 + ngl;
            const float* xwB = g_XwB + ((size_t)tB * BB + r0) * G4 + ngl;
#pragma unroll
            for (int g = 0; g < 4; ++g) {
                acc0[g] = *reinterpret_cast<const float2*>(xwF + g * HH);
                acc1[g] = *reinterpret_cast<const float2*>(xwB + g * HH);
            }
        }
        __syncthreads();

        const float* srF = sh0[b16];
        const float* srB = sh1[b16];
        const float4* upF = Upk0 + ng;
        const float4* upB = Upk1 + ng;

#pragma unroll 4
        for (int k4 = 0; k4 < HH; k4 += 4) {
            float4 hvF = *reinterpret_cast<const float4*>(srF + k4);
            float4 hvB = *reinterpret_cast<const float4*>(srB + k4);
            const float haF[4] = {hvF.x, hvF.y, hvF.z, hvF.w};
            const float haB[4] = {hvB.x, hvB.y, hvB.z, hvB.w};
#pragma unroll
            for (int kk = 0; kk < 4; ++kk) {
                const int ki = (k4 + kk) * 16;
                float4 uF0 = upF[ki];        // dir0 gates i,f
                float4 uF1 = upF[ki + 8];    // dir0 gates g,o
                float4 uB0 = upB[ki];        // dir1 gates i,f
                float4 uB1 = upB[ki + 8];    // dir1 gates g,o
                float2 hF = make_float2(haF[kk], haF[kk]);
                float2 hB = make_float2(haB[kk], haB[kk]);
                ffma2(acc0[0], make_float2(uF0.x, uF0.y), hF);
                ffma2(acc1[0], make_float2(uB0.x, uB0.y), hB);
                ffma2(acc0[1], make_float2(uF0.z, uF0.w), hF);
                ffma2(acc1[1], make_float2(uB0.z, uB0.w), hB);
                ffma2(acc0[2], make_float2(uF1.x, uF1.y), hF);
                ffma2(acc1[2], make_float2(uB1.x, uB1.y), hB);
                ffma2(acc0[3], make_float2(uF1.z, uF1.w), hF);
                ffma2(acc1[3], make_float2(uB1.z, uB1.w), hB);
            }
        }

        // gates + state update, both dirs
#pragma unroll
        for (int d = 0; d < 2; ++d) {
            float2* ac = d ? acc1 : acc0;
            const int t = d ? tB : tF;
            float c0 = sigf(ac[1].x) * cst[d].x + sigf(ac[0].x) * tanhfast(ac[2].x);
            float c1 = sigf(ac[1].y) * cst[d].y + sigf(ac[0].y) * tanhfast(ac[2].y);
            cst[d] = make_float2(c0, c1);
            float h0 = sigf(ac[3].x) * tanhfast(c0);
            float h1 = sigf(ac[3].y) * tanhfast(c1);
            float* hW = g_state + (size_t)d * 2 * BB * HH + (size_t)(par ^ 1) * BB * HH;
            __stcg(reinterpret_cast<float2*>(hW + (size_t)r0 * HH + ngl),
                   make_float2(h0, h1));
            if (write_seq)
                *reinterpret_cast<float2*>(
                    g_seq + ((size_t)t * BB + r0) * (2 * HH) + d * HH + ngl) =
                    make_float2(h0, h1);
        }

        grid_bar(grp, epoch);
    }
}

// ---------------- final dense + softmax ----------------
__global__ void final_k(const float* __restrict__ Wd, const float* __restrict__ bd,
                        float* __restrict__ out)
{
    int b = blockIdx.x, lane = threadIdx.x;
    const float* hf = g_state;                    // dir0 final h (parity buf0)
    const float* hb = g_state + 2 * BB * HH;      // dir1 final h (parity buf0)
    float acc[CC];
#pragma unroll
    for (int c = 0; c < CC; ++c) acc[c] = 0.f;
    for (int k = lane; k < 2 * HH; k += 32) {
        float hv = (k < HH) ? hf[(size_t)b * HH + k] : hb[(size_t)b * HH + k - HH];
        const float* w = Wd + (size_t)k * CC;
#pragma unroll
        for (int c = 0; c < CC; ++c) acc[c] = fmaf(hv, w[c], acc[c]);
    }
#pragma unroll
    for (int c = 0; c < CC; ++c)
#pragma unroll
        for (int o = 16; o; o >>= 1) acc[c] += __shfl_down_sync(0xffffffffu, acc[c], o);
    if (lane == 0) {
        float m = -1e30f;
#pragma unroll
        for (int c = 0; c < CC; ++c) { acc[c] += bd[c]; m = fmaxf(m, acc[c]); }
        float e[CC], s = 0.f;
#pragma unroll
        for (int c = 0; c < CC; ++c) { e[c] = expf(acc[c] - m); s += e[c]; }
        float inv = 1.f / s;
#pragma unroll
        for (int c = 0; c < CC; ++c) out[b * CC + c] = e[c] * inv;
    }
}

extern "C" void kernel_launch(void* const* d_in, const int* in_sizes, int n_in,
                              void* d_out, int out_size)
{
    const int*   x   = (const int*)  d_in[0];
    const float* emb = (const float*)d_in[1];
    const float* W1f = (const float*)d_in[2];
    const float* U1f = (const float*)d_in[3];
    const float* b1f = (const float*)d_in[4];
    const float* W1b = (const float*)d_in[5];
    const float* U1b = (const float*)d_in[6];
    const float* b1b = (const float*)d_in[7];
    const float* W2f = (const float*)d_in[8];
    const float* U2f = (const float*)d_in[9];
    const float* b2f = (const float*)d_in[10];
    const float* W2b = (const float*)d_in[11];
    const float* U2b = (const float*)d_in[12];
    const float* b2b = (const float*)d_in[13];
    const float* Wd  = (const float*)d_in[14];
    const float* bd  = (const float*)d_in[15];
    float* out = (float*)d_out;

    // 2 U slices (2*64KB) + 2 h stages (2*16*260*4) = 131072 + 33280 = 164352
    const int LSTM_SMEM = 131072 + 2 * 16 * 260 * 4;

    static int smem_set = 0;
    if (!smem_set) {
        cudaFuncSetAttribute(lstm_persist_k,
                             cudaFuncAttributeMaxDynamicSharedMemorySize, LSTM_SMEM);
        smem_set = 1;
    }

    embed_k<<<(MROWS * 32) / 256, 256>>>(x, emb);

    dim3 gg(MROWS / 128, G4 / 128);

    // layer 1
    gemm_k<<<gg, 256>>>(0, 0, W1f, b1f, DD);
    gemm_k<<<gg, 256>>>(0, 1, W1b, b1b, DD);
    lstm_persist_k<<<NCTA, 128, LSTM_SMEM>>>(U1f, U1b, 1);

    // layer 2
    gemm_k<<<gg, 256>>>(1, 0, W2f, b2f, 2 * HH);
    gemm_k<<<gg, 256>>>(1, 1, W2b, b2b, 2 * HH);
    lstm_persist_k<<<NCTA, 128, LSTM_SMEM>>>(U2f, U2b, 0);

    final_k<<<BB, 32>>>(Wd, bd, out);
}

// round 14
// speedup vs baseline: 1.0719x; 1.0719x over previous
#include <cuda_runtime.h>
#include <math.h>

#define TT 512
#define BB 128
#define DD 128
#define HH 256
#define CC 10
#define G4 1024
#define MROWS (TT*BB)
#define NCTA 128
#define NGRP 32           // CTAs per barrier group (32 nt-slices of one (dir,bt))

// ---------------- static device scratch ----------------
__device__ float g_e  [(size_t)MROWS * DD];
__device__ float g_XwF[(size_t)MROWS * G4];
__device__ float g_XwB[(size_t)MROWS * G4];
__device__ float g_seq[(size_t)MROWS * 2 * HH];
__device__ float g_state[4 * BB * HH];             // per dir: h parity buf0, buf1
__device__ unsigned g_bcount[16 * 32];
__device__ unsigned g_bepoch[16 * 32];

__device__ __forceinline__ void ffma2(float2 &d, float2 a, float2 b) {
    asm("fma.rn.f32x2 %0, %1, %2, %0;"
        : "+l"(*reinterpret_cast<unsigned long long*>(&d))
        : "l"(*reinterpret_cast<unsigned long long*>(&a)),
          "l"(*reinterpret_cast<unsigned long long*>(&b)));
}

__device__ __forceinline__ float sigf(float x) {
    return __fdividef(1.0f, 1.0f + __expf(-x));
}
__device__ __forceinline__ float tanhfast(float x) {
    return __fdividef(2.0f, 1.0f + __expf(-2.0f * x)) - 1.0f;
}

__device__ __forceinline__ void cpa16(unsigned dst, const void* src) {
    asm volatile("cp.async.cg.shared.global [%0], [%1], 16;" :: "r"(dst), "l"(src));
}
#define CPA_COMMIT() asm volatile("cp.async.commit_group;")
#define CPA_WAIT0()  asm volatile("cp.async.wait_group 0;")

__device__ __forceinline__ unsigned f2tf32(float x) {
    unsigned r; asm("cvt.rna.tf32.f32 %0, %1;" : "=r"(r) : "f"(x)); return r;
}
__device__ __forceinline__ void mma_tf32(float* c, const unsigned* a, const unsigned* b) {
    asm("mma.sync.aligned.m16n8k8.row.col.f32.tf32.tf32.f32 "
        "{%0,%1,%2,%3}, {%4,%5,%6,%7}, {%8,%9}, {%0,%1,%2,%3};"
        : "+f"(c[0]), "+f"(c[1]), "+f"(c[2]), "+f"(c[3])
        : "r"(a[0]), "r"(a[1]), "r"(a[2]), "r"(a[3]), "r"(b[0]), "r"(b[1]));
}

#define CHAIN_BAR(id) asm volatile("bar.sync %0, 64;" :: "r"(id) : "memory")

// per-chain group barrier: 32 CTA-chains sharing one (dir, batch-tile).
// Only the chain's 64 threads participate (named barrier); leader does the
// atomic arrive / epoch spin. Other chains on the SM keep issuing meanwhile.
__device__ __forceinline__ void chain_bar(int grp, int barid, bool leader,
                                          unsigned &epoch) {
    __threadfence();
    CHAIN_BAR(barid);
    if (leader) {
        unsigned* cnt = &g_bcount[grp * 32];
        unsigned* ep  = &g_bepoch[grp * 32];
        if (atomicAdd(cnt, 1) == NGRP - 1) {
            atomicExch(cnt, 0);
            __threadfence();
            atomicAdd(ep, 1);
        } else {
            while (*(volatile unsigned*)ep == epoch) { }
        }
        epoch++;
    }
    CHAIN_BAR(barid);
}

// ---------------- embedding gather ----------------
__global__ void embed_k(const int* __restrict__ x, const float* __restrict__ emb) {
    int gid = blockIdx.x * blockDim.x + threadIdx.x;
    int r  = gid >> 5;
    int c4 = gid & 31;
    int t  = r >> 7;
    int b  = r & 127;
    int tok = x[b * TT + t];
    reinterpret_cast<float4*>(g_e)[(size_t)r * 32 + c4] =
        reinterpret_cast<const float4*>(emb)[(size_t)tok * 32 + c4];
}

// ---------------- 3xTF32 tensor-core GEMM + bias (unchanged from R7) ----------------
#define AS_LD 20
#define BS_LD 136
__global__ __launch_bounds__(256) void gemm_k(int a_sel, int c_sel,
        const float* __restrict__ W, const float* __restrict__ bias, int K)
{
    const float* A = a_sel ? g_seq : g_e;
    float*       C = c_sel ? g_XwB : g_XwF;

    __shared__ __align__(16) float As[2][128][AS_LD];
    __shared__ __align__(16) float Bs[2][16][BS_LD];

    const int m0   = blockIdx.x * 128;
    const int n0   = blockIdx.y * 128;
    const int tid  = threadIdx.x;
    const int lane = tid & 31;
    const int warp = tid >> 5;
    const int gid  = lane >> 2;
    const int tig  = lane & 3;
    const int wm   = warp & 3;
    const int wn   = warp >> 2;

    const unsigned sA = (unsigned)__cvta_generic_to_shared(&As[0][0][0]);
    const unsigned sB = (unsigned)__cvta_generic_to_shared(&Bs[0][0][0]);
    const unsigned bufA = 128 * AS_LD * 4;
    const unsigned bufB = 16 * BS_LD * 4;

    float acc[2][8][4];
#pragma unroll
    for (int mb = 0; mb < 2; ++mb)
#pragma unroll
        for (int nb = 0; nb < 8; ++nb)
#pragma unroll
            for (int r = 0; r < 4; ++r) acc[mb][nb][r] = 0.f;

    const int nk = K >> 4;

    auto load_tile = [&](int buf, int kt) {
#pragma unroll
        for (int i = 0; i < 2; ++i) {
            int id = tid + i * 256;
            int r = id >> 2, kq = id & 3;
            cpa16(sA + buf * bufA + (unsigned)((r * AS_LD + kq * 4) * 4),
                  A + (size_t)(m0 + r) * K + kt + kq * 4);
        }
#pragma unroll
        for (int i = 0; i < 2; ++i) {
            int id = tid + i * 256;
            int r = id >> 5, c4 = (id & 31) * 4;
            cpa16(sB + buf * bufB + (unsigned)((r * BS_LD + c4) * 4),
                  W + (size_t)(kt + r) * G4 + n0 + c4);
        }
        CPA_COMMIT();
    };

    load_tile(0, 0);
    CPA_WAIT0();
    __syncthreads();

    for (int kt = 0; kt < nk; ++kt) {
        const int cur = kt & 1;
        const bool more = (kt + 1) < nk;
        if (more) load_tile(cur ^ 1, (kt + 1) << 4);

#pragma unroll
        for (int kh = 0; kh < 2; ++kh) {
            const int k0 = kh * 8;
            unsigned ahi[2][4], alo[2][4];
#pragma unroll
            for (int mb = 0; mb < 2; ++mb) {
                const int rbase = wm * 32 + mb * 16 + gid;
#pragma unroll
                for (int r = 0; r < 4; ++r) {
                    float v = As[cur][rbase + (r & 1) * 8][k0 + tig + (r >> 1) * 4];
                    unsigned h = f2tf32(v);
                    ahi[mb][r] = h;
                    alo[mb][r] = f2tf32(v - __uint_as_float(h));
                }
            }
#pragma unroll
            for (int nb = 0; nb < 8; ++nb) {
                const int nc = wn * 64 + nb * 8 + gid;
                float b0 = Bs[cur][k0 + tig][nc];
                float b1 = Bs[cur][k0 + tig + 4][nc];
                unsigned bh[2], bl[2];
                bh[0] = f2tf32(b0); bl[0] = f2tf32(b0 - __uint_as_float(bh[0]));
                bh[1] = f2tf32(b1); bl[1] = f2tf32(b1 - __uint_as_float(bh[1]));
#pragma unroll
                for (int mb = 0; mb < 2; ++mb) mma_tf32(acc[mb][nb], ahi[mb], bh);
#pragma unroll
                for (int mb = 0; mb < 2; ++mb) mma_tf32(acc[mb][nb], ahi[mb], bl);
#pragma unroll
                for (int mb = 0; mb < 2; ++mb) mma_tf32(acc[mb][nb], alo[mb], bh);
            }
        }
        if (more) {
            CPA_WAIT0();
            __syncthreads();
        }
    }

#pragma unroll
    for (int mb = 0; mb < 2; ++mb) {
        const int row0 = m0 + wm * 32 + mb * 16 + gid;
#pragma unroll
        for (int nb = 0; nb < 8; ++nb) {
            const int col = n0 + wn * 64 + nb * 8 + tig * 2;
            float2 bv = *reinterpret_cast<const float2*>(bias + col);
            float2 v0 = make_float2(acc[mb][nb][0] + bv.x, acc[mb][nb][1] + bv.y);
            float2 v1 = make_float2(acc[mb][nb][2] + bv.x, acc[mb][nb][3] + bv.y);
            *reinterpret_cast<float2*>(C + (size_t)row0 * G4 + col)       = v0;
            *reinterpret_cast<float2*>(C + (size_t)(row0 + 8) * G4 + col) = v1;
        }
    }
}

// ---------------- persistent bidirectional LSTM: 4 independent chains per CTA ------
// bid = bth*32 + nt (bth 0..3, nt 0..31; 8-col slice). 128 CTAs = 1/SM uniform.
// CTA hosts 4 chains c=0..3: dir = c>>1, bt = bth*2 + (c&1). Chains of the same dir
// SHARE the U smem slice (no duplication); chains are fully independent -> each
// SMSP carries 2 warps from 2 different chains, overlapping barrier/stage latency.
// Chain-private sync via named barrier (1+c, 64 threads); group barrier = atomic
// epoch over the 32 nt CTAs of (dir,bt). Thread = 1 row x 2 cols x 4 gates.
// U layout per dir: f4[k*8 + gp*4 + ng] = gates(2gp,2gp+1) for cols (c,c+1),
// c = nt*8 + ng*2  -> warp U loads are 64B broadcasts, conflict-free.
__global__ __launch_bounds__(256) void lstm_persist_k(
        const float* __restrict__ Uf, const float* __restrict__ Ub, int write_seq)
{
    extern __shared__ float smp[];
    float4* Upk = reinterpret_cast<float4*>(smp);        // [2 dirs][256k][8] float4
    float*  shb = smp + 16384;                           // 4 chains x [16][260]

    const int bid = blockIdx.x;
    const int bth = bid >> 5;          // 0..3
    const int nt  = bid & 31;          // 0..31 (8-col slice)
    const int tid = threadIdx.x;

    // load both U slices (cols [nt*8, nt*8+8), 4 gates, 256 k)
#pragma unroll
    for (int d = 0; d < 2; ++d) {
        const float* U = d ? Ub : Uf;
        float4* up = Upk + d * 2048;
        for (int i = tid; i < 2048; i += 256) {
            int k  = i >> 3;
            int f  = i & 7;
            int gp = f >> 2;
            int ng = f & 3;
            int col = nt * 8 + ng * 2;
            const float* src = U + (size_t)k * G4 + (2 * gp) * HH + col;
            float2 a = *reinterpret_cast<const float2*>(src);
            float2 b = *reinterpret_cast<const float2*>(src + HH);
            up[i] = make_float4(a.x, a.y, b.x, b.y);
        }
    }

    // zero my rows [bth*32, +32) x cols [nt*8, +8), both dirs, both parities
    for (int i = tid; i < 1024; i += 256) {
        int r  = bth * 32 + (i >> 5);
        int cc = nt * 8 + ((i >> 2) & 7);
        int d  = (i >> 1) & 1;
        int p  = i & 1;
        float* hb = g_state + (size_t)d * 2 * BB * HH + (size_t)p * BB * HH;
        __stcg(hb + (size_t)r * HH + cc, 0.f);
    }
    __syncthreads();

    // chain identity
    const int c    = tid >> 6;                 // chain 0..3
    const int ct   = tid & 63;                 // tid within chain
    const int dir  = c >> 1;
    const int btc  = bth * 2 + (c & 1);
    const int grp  = dir * 8 + btc;            // 0..15
    const int barid = 1 + c;
    const bool leader = (ct == 0);
    const int row  = ct >> 2;                  // 0..15
    const int ng   = ct & 3;                   // col pair 0..3
    const int nloc = ng * 2;
    const int ngl  = nt * 8 + nloc;
    const int r0   = btc * 16 + row;

    float* hbuf = g_state + (size_t)dir * 2 * BB * HH;
    const float* Xw = dir ? g_XwB : g_XwF;
    const float4* up = Upk + dir * 2048 + ng;
    float* shc = shb + c * 16 * 260;           // chain h stage [16][260]

    unsigned epoch = 0;
    if (leader) epoch = *(volatile unsigned*)&g_bepoch[grp * 32];
    // round 0: ensure zero-publications of ALL group members visible
    chain_bar(grp, barid, leader, epoch);

    float2 cst = make_float2(0.f, 0.f);

    for (int s = 0; s < TT; ++s) {
        const int t   = dir ? (TT - 1 - s) : s;
        const int par = s & 1;
        const float* hRead  = hbuf + (size_t)par * BB * HH;
        float*       hWrite = hbuf + (size_t)(par ^ 1) * BB * HH;

        // Xw seeds (issued before staging; consumed in k-loop epilogue)
        const float* xwb = Xw + ((size_t)t * BB + r0) * G4 + ngl;
        float2 acc[4];
#pragma unroll
        for (int g = 0; g < 4; ++g)
            acc[g] = *reinterpret_cast<const float2*>(xwb + g * HH);

        // stage this chain's h tile (16 x 256): 1024 f4 over 64 threads
#pragma unroll
        for (int i = 0; i < 16; ++i) {
            int f = ct + i * 64;
            int r = f >> 6, cq = f & 63;
            *reinterpret_cast<float4*>(&shc[r * 260 + cq * 4]) =
                __ldcg(reinterpret_cast<const float4*>(
                    hRead + (size_t)(btc * 16 + r) * HH + cq * 4));
        }
        CHAIN_BAR(barid);

        const float* sr = shc + row * 260;
#pragma unroll 8
        for (int k4 = 0; k4 < HH; k4 += 4) {
            float4 hv = *reinterpret_cast<const float4*>(sr + k4);
            const float ha[4] = {hv.x, hv.y, hv.z, hv.w};
#pragma unroll
            for (int kk = 0; kk < 4; ++kk) {
                const int ki = (k4 + kk) * 8;
                float4 u0 = up[ki];          // gates i,f cols (n,n+1)
                float4 u1 = up[ki + 4];      // gates g,o
                float2 hh = make_float2(ha[kk], ha[kk]);
                ffma2(acc[0], make_float2(u0.x, u0.y), hh);
                ffma2(acc[1], make_float2(u0.z, u0.w), hh);
                ffma2(acc[2], make_float2(u1.x, u1.y), hh);
                ffma2(acc[3], make_float2(u1.z, u1.w), hh);
            }
        }

        // gates + state update (1 row, 2 cols)
        float c0 = sigf(acc[1].x) * cst.x + sigf(acc[0].x) * tanhfast(acc[2].x);
        float c1 = sigf(acc[1].y) * cst.y + sigf(acc[0].y) * tanhfast(acc[2].y);
        cst = make_float2(c0, c1);
        float h0 = sigf(acc[3].x) * tanhfast(c0);
        float h1 = sigf(acc[3].y) * tanhfast(c1);
        __stcg(reinterpret_cast<float2*>(hWrite + (size_t)r0 * HH + ngl),
               make_float2(h0, h1));
        if (write_seq)
            *reinterpret_cast<float2*>(
                g_seq + ((size_t)t * BB + r0) * (2 * HH) + dir * HH + ngl) =
                make_float2(h0, h1);

        chain_bar(grp, barid, leader, epoch);
    }
}

// ---------------- final dense + softmax ----------------
__global__ void final_k(const float* __restrict__ Wd, const float* __restrict__ bd,
                        float* __restrict__ out)
{
    int b = blockIdx.x, lane = threadIdx.x;
    const float* hf = g_state;                    // dir0 final h (parity buf0)
    const float* hb = g_state + 2 * BB * HH;      // dir1 final h (parity buf0)
    float acc[CC];
#pragma unroll
    for (int c = 0; c < CC; ++c) acc[c] = 0.f;
    for (int k = lane; k < 2 * HH; k += 32) {
        float hv = (k < HH) ? hf[(size_t)b * HH + k] : hb[(size_t)b * HH + k - HH];
        const float* w = Wd + (size_t)k * CC;
#pragma unroll
        for (int c = 0; c < CC; ++c) acc[c] = fmaf(hv, w[c], acc[c]);
    }
#pragma unroll
    for (int c = 0; c < CC; ++c)
#pragma unroll
        for (int o = 16; o; o >>= 1) acc[c] += __shfl_down_sync(0xffffffffu, acc[c], o);
    if (lane == 0) {
        float m = -1e30f;
#pragma unroll
        for (int c = 0; c < CC; ++c) { acc[c] += bd[c]; m = fmaxf(m, acc[c]); }
        float e[CC], s = 0.f;
#pragma unroll
        for (int c = 0; c < CC; ++c) { e[c] = expf(acc[c] - m); s += e[c]; }
        float inv = 1.f / s;
#pragma unroll
        for (int c = 0; c < CC; ++c) out[b * CC + c] = e[c] * inv;
    }
}

extern "C" void kernel_launch(void* const* d_in, const int* in_sizes, int n_in,
                              void* d_out, int out_size)
{
    const int*   x   = (const int*)  d_in[0];
    const float* emb = (const float*)d_in[1];
    const float* W1f = (const float*)d_in[2];
    const float* U1f = (const float*)d_in[3];
    const float* b1f = (const float*)d_in[4];
    const float* W1b = (const float*)d_in[5];
    const float* U1b = (const float*)d_in[6];
    const float* b1b = (const float*)d_in[7];
    const float* W2f = (const float*)d_in[8];
    const float* U2f = (const float*)d_in[9];
    const float* b2f = (const float*)d_in[10];
    const float* W2b = (const float*)d_in[11];
    const float* U2b = (const float*)d_in[12];
    const float* b2b = (const float*)d_in[13];
    const float* Wd  = (const float*)d_in[14];
    const float* bd  = (const float*)d_in[15];
    float* out = (float*)d_out;

    // U (2 dirs x 32KB) + 4 chain h stages (4 x 16 x 260 x 4B) = 65536 + 66560
    const int LSTM_SMEM = 65536 + 4 * 16 * 260 * 4;

    static int smem_set = 0;
    if (!smem_set) {
        cudaFuncSetAttribute(lstm_persist_k,
                             cudaFuncAttributeMaxDynamicSharedMemorySize, LSTM_SMEM);
        smem_set = 1;
    }

    embed_k<<<(MROWS * 32) / 256, 256>>>(x, emb);

    dim3 gg(MROWS / 128, G4 / 128);

    // layer 1
    gemm_k<<<gg, 256>>>(0, 0, W1f, b1f, DD);
    gemm_k<<<gg, 256>>>(0, 1, W1b, b1b, DD);
    lstm_persist_k<<<NCTA, 256, LSTM_SMEM>>>(U1f, U1b, 1);

    // layer 2
    gemm_k<<<gg, 256>>>(1, 0, W2f, b2f, 2 * HH);
    gemm_k<<<gg, 256>>>(1, 1, W2b, b2b, 2 * HH);
    lstm_persist_k<<<NCTA, 256, LSTM_SMEM>>>(U2f, U2b, 0);

    final_k<<<BB, 32>>>(Wd, bd, out);
}

// round 15
// speedup vs baseline: 1.0950x; 1.0215x over previous
#include <cuda_runtime.h>
#include <math.h>

#define TT 512
#define BB 128
#define DD 128
#define HH 256
#define CC 10
#define G4 1024
#define MROWS (TT*BB)
#define NCTA 128
#define NGRP 16           // CTAs per barrier group (16 nt-slices of one (dir,bt))

// ---------------- static device scratch ----------------
__device__ float g_e  [(size_t)MROWS * DD];
__device__ float g_XwF[(size_t)MROWS * G4];
__device__ float g_XwB[(size_t)MROWS * G4];
__device__ float g_seq[(size_t)MROWS * 2 * HH];
__device__ float g_state[4 * BB * HH];             // per dir: h parity buf0, buf1
__device__ unsigned g_bcount[16 * 32];
__device__ unsigned g_bepoch[16 * 32];

__device__ __forceinline__ void ffma2(float2 &d, float2 a, float2 b) {
    asm("fma.rn.f32x2 %0, %1, %2, %0;"
        : "+l"(*reinterpret_cast<unsigned long long*>(&d))
        : "l"(*reinterpret_cast<unsigned long long*>(&a)),
          "l"(*reinterpret_cast<unsigned long long*>(&b)));
}

__device__ __forceinline__ float sigf(float x) {
    return __fdividef(1.0f, 1.0f + __expf(-x));
}
__device__ __forceinline__ float tanhfast(float x) {
    return __fdividef(2.0f, 1.0f + __expf(-2.0f * x)) - 1.0f;
}

__device__ __forceinline__ void cpa16(unsigned dst, const void* src) {
    asm volatile("cp.async.cg.shared.global [%0], [%1], 16;" :: "r"(dst), "l"(src));
}
#define CPA_COMMIT() asm volatile("cp.async.commit_group;")
#define CPA_WAIT0()  asm volatile("cp.async.wait_group 0;")

__device__ __forceinline__ unsigned f2tf32(float x) {
    unsigned r; asm("cvt.rna.tf32.f32 %0, %1;" : "=r"(r) : "f"(x)); return r;
}
__device__ __forceinline__ void mma_tf32(float* c, const unsigned* a, const unsigned* b) {
    asm("mma.sync.aligned.m16n8k8.row.col.f32.tf32.tf32.f32 "
        "{%0,%1,%2,%3}, {%4,%5,%6,%7}, {%8,%9}, {%0,%1,%2,%3};"
        : "+f"(c[0]), "+f"(c[1]), "+f"(c[2]), "+f"(c[3])
        : "r"(a[0]), "r"(a[1]), "r"(a[2]), "r"(a[3]), "r"(b[0]), "r"(b[1]));
}

#define CHAIN_BAR(id) asm volatile("bar.sync %0, 128;" :: "r"(id) : "memory")

// group barrier over the 16 nt-CTAs of one (dir, bt); only this chain's 128
// threads participate (named barrier) so the OTHER chain on the SM keeps issuing.
__device__ __forceinline__ void chain_bar(int grp, int barid, bool leader,
                                          unsigned &epoch) {
    __threadfence();
    CHAIN_BAR(barid);
    if (leader) {
        unsigned* cnt = &g_bcount[grp * 32];
        unsigned* ep  = &g_bepoch[grp * 32];
        if (atomicAdd(cnt, 1) == NGRP - 1) {
            atomicExch(cnt, 0);
            __threadfence();
            atomicAdd(ep, 1);
        } else {
            while (*(volatile unsigned*)ep == epoch) { }
        }
        epoch++;
    }
    CHAIN_BAR(barid);
}

// ---------------- embedding gather ----------------
__global__ void embed_k(const int* __restrict__ x, const float* __restrict__ emb) {
    int gid = blockIdx.x * blockDim.x + threadIdx.x;
    int r  = gid >> 5;
    int c4 = gid & 31;
    int t  = r >> 7;
    int b  = r & 127;
    int tok = x[b * TT + t];
    reinterpret_cast<float4*>(g_e)[(size_t)r * 32 + c4] =
        reinterpret_cast<const float4*>(emb)[(size_t)tok * 32 + c4];
}

// ---------------- 3xTF32 tensor-core GEMM + bias (unchanged from R7) ----------------
#define AS_LD 20
#define BS_LD 136
__global__ __launch_bounds__(256) void gemm_k(int a_sel, int c_sel,
        const float* __restrict__ W, const float* __restrict__ bias, int K)
{
    const float* A = a_sel ? g_seq : g_e;
    float*       C = c_sel ? g_XwB : g_XwF;

    __shared__ __align__(16) float As[2][128][AS_LD];
    __shared__ __align__(16) float Bs[2][16][BS_LD];

    const int m0   = blockIdx.x * 128;
    const int n0   = blockIdx.y * 128;
    const int tid  = threadIdx.x;
    const int lane = tid & 31;
    const int warp = tid >> 5;
    const int gid  = lane >> 2;
    const int tig  = lane & 3;
    const int wm   = warp & 3;
    const int wn   = warp >> 2;

    const unsigned sA = (unsigned)__cvta_generic_to_shared(&As[0][0][0]);
    const unsigned sB = (unsigned)__cvta_generic_to_shared(&Bs[0][0][0]);
    const unsigned bufA = 128 * AS_LD * 4;
    const unsigned bufB = 16 * BS_LD * 4;

    float acc[2][8][4];
#pragma unroll
    for (int mb = 0; mb < 2; ++mb)
#pragma unroll
        for (int nb = 0; nb < 8; ++nb)
#pragma unroll
            for (int r = 0; r < 4; ++r) acc[mb][nb][r] = 0.f;

    const int nk = K >> 4;

    auto load_tile = [&](int buf, int kt) {
#pragma unroll
        for (int i = 0; i < 2; ++i) {
            int id = tid + i * 256;
            int r = id >> 2, kq = id & 3;
            cpa16(sA + buf * bufA + (unsigned)((r * AS_LD + kq * 4) * 4),
                  A + (size_t)(m0 + r) * K + kt + kq * 4);
        }
#pragma unroll
        for (int i = 0; i < 2; ++i) {
            int id = tid + i * 256;
            int r = id >> 5, c4 = (id & 31) * 4;
            cpa16(sB + buf * bufB + (unsigned)((r * BS_LD + c4) * 4),
                  W + (size_t)(kt + r) * G4 + n0 + c4);
        }
        CPA_COMMIT();
    };

    load_tile(0, 0);
    CPA_WAIT0();
    __syncthreads();

    for (int kt = 0; kt < nk; ++kt) {
        const int cur = kt & 1;
        const bool more = (kt + 1) < nk;
        if (more) load_tile(cur ^ 1, (kt + 1) << 4);

#pragma unroll
        for (int kh = 0; kh < 2; ++kh) {
            const int k0 = kh * 8;
            unsigned ahi[2][4], alo[2][4];
#pragma unroll
            for (int mb = 0; mb < 2; ++mb) {
                const int rbase = wm * 32 + mb * 16 + gid;
#pragma unroll
                for (int r = 0; r < 4; ++r) {
                    float v = As[cur][rbase + (r & 1) * 8][k0 + tig + (r >> 1) * 4];
                    unsigned h = f2tf32(v);
                    ahi[mb][r] = h;
                    alo[mb][r] = f2tf32(v - __uint_as_float(h));
                }
            }
#pragma unroll
            for (int nb = 0; nb < 8; ++nb) {
                const int nc = wn * 64 + nb * 8 + gid;
                float b0 = Bs[cur][k0 + tig][nc];
                float b1 = Bs[cur][k0 + tig + 4][nc];
                unsigned bh[2], bl[2];
                bh[0] = f2tf32(b0); bl[0] = f2tf32(b0 - __uint_as_float(bh[0]));
                bh[1] = f2tf32(b1); bl[1] = f2tf32(b1 - __uint_as_float(bh[1]));
#pragma unroll
                for (int mb = 0; mb < 2; ++mb) mma_tf32(acc[mb][nb], ahi[mb], bh);
#pragma unroll
                for (int mb = 0; mb < 2; ++mb) mma_tf32(acc[mb][nb], ahi[mb], bl);
#pragma unroll
                for (int mb = 0; mb < 2; ++mb) mma_tf32(acc[mb][nb], alo[mb], bh);
            }
        }
        if (more) {
            CPA_WAIT0();
            __syncthreads();
        }
    }

#pragma unroll
    for (int mb = 0; mb < 2; ++mb) {
        const int row0 = m0 + wm * 32 + mb * 16 + gid;
#pragma unroll
        for (int nb = 0; nb < 8; ++nb) {
            const int col = n0 + wn * 64 + nb * 8 + tig * 2;
            float2 bv = *reinterpret_cast<const float2*>(bias + col);
            float2 v0 = make_float2(acc[mb][nb][0] + bv.x, acc[mb][nb][1] + bv.y);
            float2 v1 = make_float2(acc[mb][nb][2] + bv.x, acc[mb][nb][3] + bv.y);
            *reinterpret_cast<float2*>(C + (size_t)row0 * G4 + col)       = v0;
            *reinterpret_cast<float2*>(C + (size_t)(row0 + 8) * G4 + col) = v1;
        }
    }
}

// ---------------- persistent bidirectional LSTM: 2 chains x 128 threads ------------
// bid = dir*64 + btp*16 + nt (btp 0..3, nt 0..15; 16-col slice). 128 CTAs = 1/SM.
// CTA hosts 2 chains c=0,1 of the SAME dir, bt = btp*2+c -> chains share the 64KB
// U smem slice. Warps 0-3 = chain0, 4-7 = chain1 => every SMSP holds one warp of
// each independent chain, hiding LDS/LDG/barrier latency without extra smem traffic.
// Thread = 1 row x 2 cols x 4 gates, 256 k. U gate-paired float4 at
// [k*16 + gp*8 + ng]: each warp U load = 8 distinct float4 = 128B = 1 wavefront.
// Staging: 8 LDG.128/thread (R7 level). Group barrier: NGRP=16, atomic epoch.
__global__ __launch_bounds__(256) void lstm_persist_k(
        const float* __restrict__ Uf, const float* __restrict__ Ub, int write_seq)
{
    extern __shared__ float smp[];
    float4* Upk = reinterpret_cast<float4*>(smp);        // [256 k][16] float4 (64KB)
    float*  shb = smp + 16384;                           // 2 chains x [16][260]

    const int bid = blockIdx.x;
    const int dir = bid >> 6;
    const int btp = (bid >> 4) & 3;
    const int nt  = bid & 15;
    const int tid = threadIdx.x;

    const float* U  = dir ? Ub : Uf;
    const float* Xw = dir ? g_XwB : g_XwF;
    float* hbuf = g_state + (size_t)dir * 2 * BB * HH;

    // U slice: cols [nt*16,+16), gate-pair float4 blocked per k (16 f4 = 256B/k):
    // Upk[k*16 + gp*8 + ng] = (U[k][2gp*HH+c], U[k][2gp*HH+c+1],
    //                          U[k][(2gp+1)*HH+c], U[k][(2gp+1)*HH+c+1]), c=nt*16+ng*2
    for (int i = tid; i < 4096; i += 256) {
        int k  = i >> 4;
        int f  = i & 15;
        int gp = f >> 3;
        int ng = f & 7;
        int col = nt * 16 + ng * 2;
        const float* src = U + (size_t)k * G4 + (2 * gp) * HH + col;
        float2 a = *reinterpret_cast<const float2*>(src);
        float2 b = *reinterpret_cast<const float2*>(src + HH);
        Upk[i] = make_float4(a.x, a.y, b.x, b.y);
    }

    // zero rows [btp*32,+32) x cols [nt*16,+16), both parities
    for (int i = tid; i < 1024; i += 256) {
        int r  = btp * 32 + (i >> 5);
        int cc = nt * 16 + ((i >> 1) & 15);
        int p  = i & 1;
        __stcg(hbuf + (size_t)p * BB * HH + (size_t)r * HH + cc, 0.f);
    }
    __syncthreads();

    // chain identity
    const int c     = tid >> 7;                // chain 0/1
    const int ct    = tid & 127;               // tid within chain
    const int btc   = btp * 2 + c;
    const int grp   = dir * 8 + btc;           // 0..15
    const int barid = 1 + c;
    const bool leader = (ct == 0);
    const int row   = ct >> 3;                 // 0..15
    const int ng    = ct & 7;                  // col pair 0..7
    const int nloc  = ng * 2;
    const int ngl   = nt * 16 + nloc;
    const int r0    = btc * 16 + row;

    float* shc = shb + c * 16 * 260;           // chain h stage [16][260]

    unsigned epoch = 0;
    if (leader) epoch = *(volatile unsigned*)&g_bepoch[grp * 32];
    chain_bar(grp, barid, leader, epoch);      // zeros visible group-wide

    float2 cst = make_float2(0.f, 0.f);

    for (int s = 0; s < TT; ++s) {
        const int t   = dir ? (TT - 1 - s) : s;
        const int par = s & 1;
        const float* hRead  = hbuf + (size_t)par * BB * HH;
        float*       hWrite = hbuf + (size_t)(par ^ 1) * BB * HH;

        // Xw seeds (LDG issued first; consumed after k-loop)
        const float* xwb = Xw + ((size_t)t * BB + r0) * G4 + ngl;
        float2 acc[4];
#pragma unroll
        for (int g = 0; g < 4; ++g)
            acc[g] = *reinterpret_cast<const float2*>(xwb + g * HH);

        // stage chain h tile (16 x 256): 1024 f4 over 128 threads = 8/thread
#pragma unroll
        for (int i = 0; i < 8; ++i) {
            int f = ct + i * 128;
            int r = f >> 6, cq = f & 63;
            *reinterpret_cast<float4*>(&shc[r * 260 + cq * 4]) =
                __ldcg(reinterpret_cast<const float4*>(
                    hRead + (size_t)(btc * 16 + r) * HH + cq * 4));
        }
        CHAIN_BAR(barid);

        const float* sr = shc + row * 260;
        const float4* up = Upk + ng;
#pragma unroll 8
        for (int k4 = 0; k4 < HH; k4 += 4) {
            float4 hv = *reinterpret_cast<const float4*>(sr + k4);
            const float ha[4] = {hv.x, hv.y, hv.z, hv.w};
#pragma unroll
            for (int kk = 0; kk < 4; ++kk) {
                const int ki = (k4 + kk) * 16;
                float4 u0 = up[ki];          // gates i,f for cols (n, n+1)
                float4 u1 = up[ki + 8];      // gates g,o
                float2 hh = make_float2(ha[kk], ha[kk]);
                ffma2(acc[0], make_float2(u0.x, u0.y), hh);
                ffma2(acc[1], make_float2(u0.z, u0.w), hh);
                ffma2(acc[2], make_float2(u1.x, u1.y), hh);
                ffma2(acc[3], make_float2(u1.z, u1.w), hh);
            }
        }

        // gates + state update (1 row, 2 cols)
        float c0 = sigf(acc[1].x) * cst.x + sigf(acc[0].x) * tanhfast(acc[2].x);
        float c1 = sigf(acc[1].y) * cst.y + sigf(acc[0].y) * tanhfast(acc[2].y);
        cst = make_float2(c0, c1);
        float h0 = sigf(acc[3].x) * tanhfast(c0);
        float h1 = sigf(acc[3].y) * tanhfast(c1);
        __stcg(reinterpret_cast<float2*>(hWrite + (size_t)r0 * HH + ngl),
               make_float2(h0, h1));
        if (write_seq)
            *reinterpret_cast<float2*>(
                g_seq + ((size_t)t * BB + r0) * (2 * HH) + dir * HH + ngl) =
                make_float2(h0, h1);

        chain_bar(grp, barid, leader, epoch);
    }
}

// ---------------- final dense + softmax ----------------
__global__ void final_k(const float* __restrict__ Wd, const float* __restrict__ bd,
                        float* __restrict__ out)
{
    int b = blockIdx.x, lane = threadIdx.x;
    const float* hf = g_state;                    // dir0 final h (parity buf0)
    const float* hb = g_state + 2 * BB * HH;      // dir1 final h (parity buf0)
    float acc[CC];
#pragma unroll
    for (int c = 0; c < CC; ++c) acc[c] = 0.f;
    for (int k = lane; k < 2 * HH; k += 32) {
        float hv = (k < HH) ? hf[(size_t)b * HH + k] : hb[(size_t)b * HH + k - HH];
        const float* w = Wd + (size_t)k * CC;
#pragma unroll
        for (int c = 0; c < CC; ++c) acc[c] = fmaf(hv, w[c], acc[c]);
    }
#pragma unroll
    for (int c = 0; c < CC; ++c)
#pragma unroll
        for (int o = 16; o; o >>= 1) acc[c] += __shfl_down_sync(0xffffffffu, acc[c], o);
    if (lane == 0) {
        float m = -1e30f;
#pragma unroll
        for (int c = 0; c < CC; ++c) { acc[c] += bd[c]; m = fmaxf(m, acc[c]); }
        float e[CC], s = 0.f;
#pragma unroll
        for (int c = 0; c < CC; ++c) { e[c] = expf(acc[c] - m); s += e[c]; }
        float inv = 1.f / s;
#pragma unroll
        for (int c = 0; c < CC; ++c) out[b * CC + c] = e[c] * inv;
    }
}

extern "C" void kernel_launch(void* const* d_in, const int* in_sizes, int n_in,
                              void* d_out, int out_size)
{
    const int*   x   = (const int*)  d_in[0];
    const float* emb = (const float*)d_in[1];
    const float* W1f = (const float*)d_in[2];
    const float* U1f = (const float*)d_in[3];
    const float* b1f = (const float*)d_in[4];
    const float* W1b = (const float*)d_in[5];
    const float* U1b = (const float*)d_in[6];
    const float* b1b = (const float*)d_in[7];
    const float* W2f = (const float*)d_in[8];
    const float* U2f = (const float*)d_in[9];
    const float* b2f = (const float*)d_in[10];
    const float* W2b = (const float*)d_in[11];
    const float* U2b = (const float*)d_in[12];
    const float* b2b = (const float*)d_in[13];
    const float* Wd  = (const float*)d_in[14];
    const float* bd  = (const float*)d_in[15];
    float* out = (float*)d_out;

    // U 64KB + 2 chain h stages (2 x 16 x 260 x 4B) = 65536 + 33280 = 98816
    const int LSTM_SMEM = 65536 + 2 * 16 * 260 * 4;

    static int smem_set = 0;
    if (!smem_set) {
        cudaFuncSetAttribute(lstm_persist_k,
                             cudaFuncAttributeMaxDynamicSharedMemorySize, LSTM_SMEM);
        smem_set = 1;
    }

    embed_k<<<(MROWS * 32) / 256, 256>>>(x, emb);

    dim3 gg(MROWS / 128, G4 / 128);

    // layer 1
    gemm_k<<<gg, 256>>>(0, 0, W1f, b1f, DD);
    gemm_k<<<gg, 256>>>(0, 1, W1b, b1b, DD);
    lstm_persist_k<<<NCTA, 256, LSTM_SMEM>>>(U1f, U1b, 1);

    // layer 2
    gemm_k<<<gg, 256>>>(1, 0, W2f, b2f, 2 * HH);
    gemm_k<<<gg, 256>>>(1, 1, W2b, b2b, 2 * HH);
    lstm_persist_k<<<NCTA, 256, LSTM_SMEM>>>(U2f, U2b, 0);

    final_k<<<BB, 32>>>(Wd, bd, out);
}

// round 16
// speedup vs baseline: 1.4331x; 1.3088x over previous
#include <cuda_runtime.h>
#include <math.h>

#define TT 512
#define BB 128
#define DD 128
#define HH 256
#define CC 10
#define G4 1024
#define MROWS (TT*BB)
#define NCTA 128
#define NGRP 8            // CTAs per barrier group = one (dir, batch-tile)

// ---------------- static device scratch (no runtime allocation) ----------------
__device__ float g_e  [(size_t)MROWS * DD];
__device__ float g_XwF[(size_t)MROWS * G4];
__device__ float g_XwB[(size_t)MROWS * G4];
__device__ float g_seq[(size_t)MROWS * 2 * HH];
__device__ float g_state[4 * BB * HH];             // per dir: h parity buf0, buf1
__device__ unsigned g_flags[NCTA * 32];            // per-CTA epoch flag, 128B lines

__device__ __forceinline__ void ffma2(float2 &d, float2 a, float2 b) {
    asm("fma.rn.f32x2 %0, %1, %2, %0;"
        : "+l"(*reinterpret_cast<unsigned long long*>(&d))
        : "l"(*reinterpret_cast<unsigned long long*>(&a)),
          "l"(*reinterpret_cast<unsigned long long*>(&b)));
}

__device__ __forceinline__ float sigf(float x) {
    return __fdividef(1.0f, 1.0f + __expf(-x));
}
__device__ __forceinline__ float tanhfast(float x) {
    return __fdividef(2.0f, 1.0f + __expf(-2.0f * x)) - 1.0f;
}

__device__ __forceinline__ void cpa16(unsigned dst, const void* src) {
    asm volatile("cp.async.cg.shared.global [%0], [%1], 16;" :: "r"(dst), "l"(src));
}
#define CPA_COMMIT() asm volatile("cp.async.commit_group;")
#define CPA_WAIT0()  asm volatile("cp.async.wait_group 0;")

__device__ __forceinline__ unsigned f2tf32(float x) {
    unsigned r; asm("cvt.rna.tf32.f32 %0, %1;" : "=r"(r) : "f"(x)); return r;
}
__device__ __forceinline__ void mma_tf32(float* c, const unsigned* a, const unsigned* b) {
    asm("mma.sync.aligned.m16n8k8.row.col.f32.tf32.tf32.f32 "
        "{%0,%1,%2,%3}, {%4,%5,%6,%7}, {%8,%9}, {%0,%1,%2,%3};"
        : "+f"(c[0]), "+f"(c[1]), "+f"(c[2]), "+f"(c[3])
        : "r"(a[0]), "r"(a[1]), "r"(a[2]), "r"(a[3]), "r"(b[0]), "r"(b[1]));
}

// flag-based group barrier: arrival = 1 release-store to own flag (no atomic
// serialization); wait = warp 0 polls the 8 group flags in PARALLEL (one lane per
// flag, one LDG wavefront per poll, vote). Flags are monotone epochs.
__device__ __forceinline__ void grid_bar(int bid, int grp, unsigned target) {
    __threadfence();
    __syncthreads();
    if (threadIdx.x < 32) {
        if (threadIdx.x == 0)
            asm volatile("st.release.gpu.global.u32 [%0], %1;"
                         :: "l"(&g_flags[bid * 32]), "r"(target) : "memory");
        const unsigned* fp = &g_flags[(grp * NGRP + (threadIdx.x & 7)) * 32];
        unsigned v;
        do {
            asm volatile("ld.acquire.gpu.global.u32 %0, [%1];" : "=r"(v) : "l"(fp));
        } while (!__all_sync(0xffffffffu, (int)(v - target) >= 0));
    }
    __syncthreads();
}

// ---------------- embedding gather: g_e[t*B+b, :] = emb[x[b,t], :] ----------------
__global__ void embed_k(const int* __restrict__ x, const float* __restrict__ emb) {
    int gid = blockIdx.x * blockDim.x + threadIdx.x;
    int r  = gid >> 5;
    int c4 = gid & 31;
    int t  = r >> 7;
    int b  = r & 127;
    int tok = x[b * TT + t];
    reinterpret_cast<float4*>(g_e)[(size_t)r * 32 + c4] =
        reinterpret_cast<const float4*>(emb)[(size_t)tok * 32 + c4];
}

// ---------------- 3xTF32 tensor-core GEMM + bias (unchanged from R7) ----------------
#define AS_LD 20
#define BS_LD 136
__global__ __launch_bounds__(256) void gemm_k(int a_sel, int c_sel,
        const float* __restrict__ W, const float* __restrict__ bias, int K)
{
    const float* A = a_sel ? g_seq : g_e;
    float*       C = c_sel ? g_XwB : g_XwF;

    __shared__ __align__(16) float As[2][128][AS_LD];
    __shared__ __align__(16) float Bs[2][16][BS_LD];

    const int m0   = blockIdx.x * 128;
    const int n0   = blockIdx.y * 128;
    const int tid  = threadIdx.x;
    const int lane = tid & 31;
    const int warp = tid >> 5;
    const int gid  = lane >> 2;
    const int tig  = lane & 3;
    const int wm   = warp & 3;
    const int wn   = warp >> 2;

    const unsigned sA = (unsigned)__cvta_generic_to_shared(&As[0][0][0]);
    const unsigned sB = (unsigned)__cvta_generic_to_shared(&Bs[0][0][0]);
    const unsigned bufA = 128 * AS_LD * 4;
    const unsigned bufB = 16 * BS_LD * 4;

    float acc[2][8][4];
#pragma unroll
    for (int mb = 0; mb < 2; ++mb)
#pragma unroll
        for (int nb = 0; nb < 8; ++nb)
#pragma unroll
            for (int r = 0; r < 4; ++r) acc[mb][nb][r] = 0.f;

    const int nk = K >> 4;

    auto load_tile = [&](int buf, int kt) {
#pragma unroll
        for (int i = 0; i < 2; ++i) {
            int id = tid + i * 256;
            int r = id >> 2, kq = id & 3;
            cpa16(sA + buf * bufA + (unsigned)((r * AS_LD + kq * 4) * 4),
                  A + (size_t)(m0 + r) * K + kt + kq * 4);
        }
#pragma unroll
        for (int i = 0; i < 2; ++i) {
            int id = tid + i * 256;
            int r = id >> 5, c4 = (id & 31) * 4;
            cpa16(sB + buf * bufB + (unsigned)((r * BS_LD + c4) * 4),
                  W + (size_t)(kt + r) * G4 + n0 + c4);
        }
        CPA_COMMIT();
    };

    load_tile(0, 0);
    CPA_WAIT0();
    __syncthreads();

    for (int kt = 0; kt < nk; ++kt) {
        const int cur = kt & 1;
        const bool more = (kt + 1) < nk;
        if (more) load_tile(cur ^ 1, (kt + 1) << 4);

#pragma unroll
        for (int kh = 0; kh < 2; ++kh) {
            const int k0 = kh * 8;
            unsigned ahi[2][4], alo[2][4];
#pragma unroll
            for (int mb = 0; mb < 2; ++mb) {
                const int rbase = wm * 32 + mb * 16 + gid;
#pragma unroll
                for (int r = 0; r < 4; ++r) {
                    float v = As[cur][rbase + (r & 1) * 8][k0 + tig + (r >> 1) * 4];
                    unsigned h = f2tf32(v);
                    ahi[mb][r] = h;
                    alo[mb][r] = f2tf32(v - __uint_as_float(h));
                }
            }
#pragma unroll
            for (int nb = 0; nb < 8; ++nb) {
                const int nc = wn * 64 + nb * 8 + gid;
                float b0 = Bs[cur][k0 + tig][nc];
                float b1 = Bs[cur][k0 + tig + 4][nc];
                unsigned bh[2], bl[2];
                bh[0] = f2tf32(b0); bl[0] = f2tf32(b0 - __uint_as_float(bh[0]));
                bh[1] = f2tf32(b1); bl[1] = f2tf32(b1 - __uint_as_float(bh[1]));
#pragma unroll
                for (int mb = 0; mb < 2; ++mb) mma_tf32(acc[mb][nb], ahi[mb], bh);
#pragma unroll
                for (int mb = 0; mb < 2; ++mb) mma_tf32(acc[mb][nb], ahi[mb], bl);
#pragma unroll
                for (int mb = 0; mb < 2; ++mb) mma_tf32(acc[mb][nb], alo[mb], bh);
            }
        }
        if (more) {
            CPA_WAIT0();
            __syncthreads();
        }
    }

#pragma unroll
    for (int mb = 0; mb < 2; ++mb) {
        const int row0 = m0 + wm * 32 + mb * 16 + gid;
#pragma unroll
        for (int nb = 0; nb < 8; ++nb) {
            const int col = n0 + wn * 64 + nb * 8 + tig * 2;
            float2 bv = *reinterpret_cast<const float2*>(bias + col);
            float2 v0 = make_float2(acc[mb][nb][0] + bv.x, acc[mb][nb][1] + bv.y);
            float2 v1 = make_float2(acc[mb][nb][2] + bv.x, acc[mb][nb][3] + bv.y);
            *reinterpret_cast<float2*>(C + (size_t)row0 * G4 + col)       = v0;
            *reinterpret_cast<float2*>(C + (size_t)(row0 + 8) * G4 + col) = v1;
        }
    }
}

// ---------------- persistent bidirectional LSTM (R7 structure, flag barrier) --------
// bid = dir*64 + bt*8 + nt; group = bid>>3 = dir*8+bt (the 8 CTAs exchanging h).
__global__ __launch_bounds__(128) void lstm_persist_k(
        const float* __restrict__ Uf, const float* __restrict__ Ub, int write_seq)
{
    extern __shared__ float Us[];                 // [256][128] U slice
    __shared__ __align__(16) float sh[16][260];   // h tile stage

    const int bid = blockIdx.x;
    const int dir = bid >> 6;
    const int bt  = (bid >> 3) & 7;
    const int nt  = bid & 7;
    const int grp = bid >> 3;                     // 0..15
    const int tid = threadIdx.x;

    const float* U  = dir ? Ub : Uf;
    const float* Xw = dir ? g_XwB : g_XwF;
    float* hbuf = g_state + (size_t)dir * 2 * BB * HH;

    // base epoch: all flags equal at kernel entry (monotone across replays)
    const unsigned base = *(volatile unsigned*)&g_flags[bid * 32];

    // load U slice: Us[k*128 + g*32 + ln] = U[k*G4 + g*HH + nt*32 + ln]
    for (int i = tid; i < 256 * 32; i += 128) {
        int k = i >> 5;
        int col = (i & 31) * 4;
        int g = col >> 5, ln = col & 31;
        *reinterpret_cast<float4*>(&Us[k * 128 + col]) =
            *reinterpret_cast<const float4*>(U + (size_t)k * G4 + g * HH + nt * 32 + ln);
    }

    // zero my (bt, nt) patch of both h parity buffers
    for (int i = tid; i < 512; i += 128) {
        int r  = bt * 16 + (i >> 5);
        int cc = nt * 32 + (i & 31);
        __stcg(hbuf + (size_t)r * HH + cc, 0.f);
        __stcg(hbuf + (size_t)BB * HH + (size_t)r * HH + cc, 0.f);
    }

    grid_bar(bid, grp, base + 1);

    const int b_half = tid >> 4;
    const int n_grp  = tid & 15;
    const int nloc   = n_grp * 2;
    const int ngl    = nt * 32 + nloc;
    const int r0     = bt * 16 + b_half * 2;

    float2 cst[2] = {make_float2(0.f, 0.f), make_float2(0.f, 0.f)};

    for (int s = 0; s < TT; ++s) {
        const int t   = dir ? (TT - 1 - s) : s;
        const int par = s & 1;
        const float* hRead  = hbuf + (size_t)par * BB * HH;
        float*       hWrite = hbuf + (size_t)(par ^ 1) * BB * HH;

        // stage h tile (16 rows x 256) from L2
#pragma unroll
        for (int i = 0; i < 8; ++i) {
            int f = tid + i * 128;
            int r = f >> 6, cq = f & 63;
            *reinterpret_cast<float4*>(&sh[r][cq * 4]) =
                __ldcg(reinterpret_cast<const float4*>(
                    hRead + (size_t)(bt * 16 + r) * HH + cq * 4));
        }
        const float* xw0 = Xw + ((size_t)t * BB + r0) * G4 + ngl;
        const float* xw1 = xw0 + G4;
        float2 x0[4], x1[4];
#pragma unroll
        for (int g = 0; g < 4; ++g) {
            x0[g] = *reinterpret_cast<const float2*>(xw0 + g * HH);
            x1[g] = *reinterpret_cast<const float2*>(xw1 + g * HH);
        }
        __syncthreads();

        float2 acc[4][2];
#pragma unroll
        for (int g = 0; g < 4; ++g) {
            acc[g][0] = make_float2(0.f, 0.f);
            acc[g][1] = make_float2(0.f, 0.f);
        }

        const float* sr0 = sh[b_half * 2];
        const float* sr1 = sh[b_half * 2 + 1];
        const float* Up  = Us + nloc;

#pragma unroll 4
        for (int k4 = 0; k4 < HH; k4 += 4) {
            float4 h0v = *reinterpret_cast<const float4*>(sr0 + k4);
            float4 h1v = *reinterpret_cast<const float4*>(sr1 + k4);
            const float h0a[4] = {h0v.x, h0v.y, h0v.z, h0v.w};
            const float h1a[4] = {h1v.x, h1v.y, h1v.z, h1v.w};
#pragma unroll
            for (int kk = 0; kk < 4; ++kk) {
                const float* row = Up + (size_t)(k4 + kk) * 128;
                float2 hh0 = make_float2(h0a[kk], h0a[kk]);
                float2 hh1 = make_float2(h1a[kk], h1a[kk]);
#pragma unroll
                for (int g = 0; g < 4; ++g) {
                    float2 u2 = *reinterpret_cast<const float2*>(row + g * 32);
                    ffma2(acc[g][0], u2, hh0);
                    ffma2(acc[g][1], u2, hh1);
                }
            }
        }

#pragma unroll
        for (int bb = 0; bb < 2; ++bb) {
            const float2* xg = bb ? x1 : x0;
            float zi0 = acc[0][bb].x + xg[0].x, zi1 = acc[0][bb].y + xg[0].y;
            float zf0 = acc[1][bb].x + xg[1].x, zf1 = acc[1][bb].y + xg[1].y;
            float zg0 = acc[2][bb].x + xg[2].x, zg1 = acc[2][bb].y + xg[2].y;
            float zo0 = acc[3][bb].x + xg[3].x, zo1 = acc[3][bb].y + xg[3].y;
            float c0 = sigf(zf0) * cst[bb].x + sigf(zi0) * tanhfast(zg0);
            float c1 = sigf(zf1) * cst[bb].y + sigf(zi1) * tanhfast(zg1);
            cst[bb] = make_float2(c0, c1);
            float h0 = sigf(zo0) * tanhfast(c0);
            float h1 = sigf(zo1) * tanhfast(c1);
            int r = r0 + bb;
            __stcg(reinterpret_cast<float2*>(hWrite + (size_t)r * HH + ngl),
                   make_float2(h0, h1));
            if (write_seq)
                *reinterpret_cast<float2*>(
                    g_seq + ((size_t)t * BB + r) * (2 * HH) + dir * HH + ngl) =
                    make_float2(h0, h1);
        }

        grid_bar(bid, grp, base + (unsigned)s + 2);
    }
}

// ---------------- final dense + softmax ----------------
__global__ void final_k(const float* __restrict__ Wd, const float* __restrict__ bd,
                        float* __restrict__ out)
{
    int b = blockIdx.x, lane = threadIdx.x;
    const float* hf = g_state;                    // dir0 final h (parity buf0)
    const float* hb = g_state + 2 * BB * HH;      // dir1 final h (parity buf0)
    float acc[CC];
#pragma unroll
    for (int c = 0; c < CC; ++c) acc[c] = 0.f;
    for (int k = lane; k < 2 * HH; k += 32) {
        float hv = (k < HH) ? hf[(size_t)b * HH + k] : hb[(size_t)b * HH + k - HH];
        const float* w = Wd + (size_t)k * CC;
#pragma unroll
        for (int c = 0; c < CC; ++c) acc[c] = fmaf(hv, w[c], acc[c]);
    }
#pragma unroll
    for (int c = 0; c < CC; ++c)
#pragma unroll
        for (int o = 16; o; o >>= 1) acc[c] += __shfl_down_sync(0xffffffffu, acc[c], o);
    if (lane == 0) {
        float m = -1e30f;
#pragma unroll
        for (int c = 0; c < CC; ++c) { acc[c] += bd[c]; m = fmaxf(m, acc[c]); }
        float e[CC], s = 0.f;
#pragma unroll
        for (int c = 0; c < CC; ++c) { e[c] = expf(acc[c] - m); s += e[c]; }
        float inv = 1.f / s;
#pragma unroll
        for (int c = 0; c < CC; ++c) out[b * CC + c] = e[c] * inv;
    }
}

extern "C" void kernel_launch(void* const* d_in, const int* in_sizes, int n_in,
                              void* d_out, int out_size)
{
    const int*   x   = (const int*)  d_in[0];
    const float* emb = (const float*)d_in[1];
    const float* W1f = (const float*)d_in[2];
    const float* U1f = (const float*)d_in[3];
    const float* b1f = (const float*)d_in[4];
    const float* W1b = (const float*)d_in[5];
    const float* U1b = (const float*)d_in[6];
    const float* b1b = (const float*)d_in[7];
    const float* W2f = (const float*)d_in[8];
    const float* U2f = (const float*)d_in[9];
    const float* b2f = (const float*)d_in[10];
    const float* W2b = (const float*)d_in[11];
    const float* U2b = (const float*)d_in[12];
    const float* b2b = (const float*)d_in[13];
    const float* Wd  = (const float*)d_in[14];
    const float* bd  = (const float*)d_in[15];
    float* out = (float*)d_out;

    static int smem_set = 0;
    if (!smem_set) {
        cudaFuncSetAttribute(lstm_persist_k,
                             cudaFuncAttributeMaxDynamicSharedMemorySize, 131072);
        smem_set = 1;
    }

    embed_k<<<(MROWS * 32) / 256, 256>>>(x, emb);

    dim3 gg(MROWS / 128, G4 / 128);

    // layer 1
    gemm_k<<<gg, 256>>>(0, 0, W1f, b1f, DD);
    gemm_k<<<gg, 256>>>(0, 1, W1b, b1b, DD);
    lstm_persist_k<<<NCTA, 128, 131072>>>(U1f, U1b, 1);

    // layer 2
    gemm_k<<<gg, 256>>>(1, 0, W2f, b2f, 2 * HH);
    gemm_k<<<gg, 256>>>(1, 1, W2b, b2b, 2 * HH);
    lstm_persist_k<<<NCTA, 128, 131072>>>(U2f, U2b, 0);

    final_k<<<BB, 32>>>(Wd, bd, out);
}

// round 17
// speedup vs baseline: 1.9543x; 1.3637x over previous
#include <cuda_runtime.h>
#include <math.h>

#define TT 512
#define BB 128
#define DD 128
#define HH 256
#define CC 10
#define G4 1024
#define MROWS (TT*BB)
#define NCTA 128
#define NGRP 8            // CTAs per barrier group = one (dir, batch-tile)

// ---------------- static device scratch (no runtime allocation) ----------------
__device__ float g_e  [(size_t)MROWS * DD];
__device__ float g_XwF[(size_t)MROWS * G4];
__device__ float g_XwB[(size_t)MROWS * G4];
__device__ float g_seq[(size_t)MROWS * 2 * HH];
__device__ float g_state[4 * BB * HH];             // per dir: h parity buf0, buf1
__device__ unsigned g_flags[NCTA * 32];            // per-CTA epoch flag, 128B lines

__device__ __forceinline__ float sigf(float x) {
    return __fdividef(1.0f, 1.0f + __expf(-x));
}
__device__ __forceinline__ float tanhfast(float x) {
    return __fdividef(2.0f, 1.0f + __expf(-2.0f * x)) - 1.0f;
}

__device__ __forceinline__ void cpa16(unsigned dst, const void* src) {
    asm volatile("cp.async.cg.shared.global [%0], [%1], 16;" :: "r"(dst), "l"(src));
}
#define CPA_COMMIT() asm volatile("cp.async.commit_group;")
#define CPA_WAIT0()  asm volatile("cp.async.wait_group 0;")

__device__ __forceinline__ unsigned f2tf32(float x) {
    unsigned r; asm("cvt.rna.tf32.f32 %0, %1;" : "=r"(r) : "f"(x)); return r;
}
__device__ __forceinline__ void mma_tf32(float* c, const unsigned* a, const unsigned* b) {
    asm("mma.sync.aligned.m16n8k8.row.col.f32.tf32.tf32.f32 "
        "{%0,%1,%2,%3}, {%4,%5,%6,%7}, {%8,%9}, {%0,%1,%2,%3};"
        : "+f"(c[0]), "+f"(c[1]), "+f"(c[2]), "+f"(c[3])
        : "r"(a[0]), "r"(a[1]), "r"(a[2]), "r"(a[3]), "r"(b[0]), "r"(b[1]));
}

// flag-based group barrier (R16, measured-best): arrival = 1 release-store,
// wait = warp 0 polls 8 group flags in parallel + vote. Monotone epochs.
__device__ __forceinline__ void grid_bar(int bid, int grp, unsigned target) {
    __threadfence();
    __syncthreads();
    if (threadIdx.x < 32) {
        if (threadIdx.x == 0)
            asm volatile("st.release.gpu.global.u32 [%0], %1;"
                         :: "l"(&g_flags[bid * 32]), "r"(target) : "memory");
        const unsigned* fp = &g_flags[(grp * NGRP + (threadIdx.x & 7)) * 32];
        unsigned v;
        do {
            asm volatile("ld.acquire.gpu.global.u32 %0, [%1];" : "=r"(v) : "l"(fp));
        } while (!__all_sync(0xffffffffu, (int)(v - target) >= 0));
    }
    __syncthreads();
}

// ---------------- embedding gather ----------------
__global__ void embed_k(const int* __restrict__ x, const float* __restrict__ emb) {
    int gid = blockIdx.x * blockDim.x + threadIdx.x;
    int r  = gid >> 5;
    int c4 = gid & 31;
    int t  = r >> 7;
    int b  = r & 127;
    int tok = x[b * TT + t];
    reinterpret_cast<float4*>(g_e)[(size_t)r * 32 + c4] =
        reinterpret_cast<const float4*>(emb)[(size_t)tok * 32 + c4];
}

// ---------------- 3xTF32 tensor-core GEMM + bias (unchanged from R7/R16) ------------
#define AS_LD 20
#define BS_LD 136
__global__ __launch_bounds__(256) void gemm_k(int a_sel, int c_sel,
        const float* __restrict__ W, const float* __restrict__ bias, int K)
{
    const float* A = a_sel ? g_seq : g_e;
    float*       C = c_sel ? g_XwB : g_XwF;

    __shared__ __align__(16) float As[2][128][AS_LD];
    __shared__ __align__(16) float Bs[2][16][BS_LD];

    const int m0   = blockIdx.x * 128;
    const int n0   = blockIdx.y * 128;
    const int tid  = threadIdx.x;
    const int lane = tid & 31;
    const int warp = tid >> 5;
    const int gid  = lane >> 2;
    const int tig  = lane & 3;
    const int wm   = warp & 3;
    const int wn   = warp >> 2;

    const unsigned sA = (unsigned)__cvta_generic_to_shared(&As[0][0][0]);
    const unsigned sB = (unsigned)__cvta_generic_to_shared(&Bs[0][0][0]);
    const unsigned bufA = 128 * AS_LD * 4;
    const unsigned bufB = 16 * BS_LD * 4;

    float acc[2][8][4];
#pragma unroll
    for (int mb = 0; mb < 2; ++mb)
#pragma unroll
        for (int nb = 0; nb < 8; ++nb)
#pragma unroll
            for (int r = 0; r < 4; ++r) acc[mb][nb][r] = 0.f;

    const int nk = K >> 4;

    auto load_tile = [&](int buf, int kt) {
#pragma unroll
        for (int i = 0; i < 2; ++i) {
            int id = tid + i * 256;
            int r = id >> 2, kq = id & 3;
            cpa16(sA + buf * bufA + (unsigned)((r * AS_LD + kq * 4) * 4),
                  A + (size_t)(m0 + r) * K + kt + kq * 4);
        }
#pragma unroll
        for (int i = 0; i < 2; ++i) {
            int id = tid + i * 256;
            int r = id >> 5, c4 = (id & 31) * 4;
            cpa16(sB + buf * bufB + (unsigned)((r * BS_LD + c4) * 4),
                  W + (size_t)(kt + r) * G4 + n0 + c4);
        }
        CPA_COMMIT();
    };

    load_tile(0, 0);
    CPA_WAIT0();
    __syncthreads();

    for (int kt = 0; kt < nk; ++kt) {
        const int cur = kt & 1;
        const bool more = (kt + 1) < nk;
        if (more) load_tile(cur ^ 1, (kt + 1) << 4);

#pragma unroll
        for (int kh = 0; kh < 2; ++kh) {
            const int k0 = kh * 8;
            unsigned ahi[2][4], alo[2][4];
#pragma unroll
            for (int mb = 0; mb < 2; ++mb) {
                const int rbase = wm * 32 + mb * 16 + gid;
#pragma unroll
                for (int r = 0; r < 4; ++r) {
                    float v = As[cur][rbase + (r & 1) * 8][k0 + tig + (r >> 1) * 4];
                    unsigned h = f2tf32(v);
                    ahi[mb][r] = h;
                    alo[mb][r] = f2tf32(v - __uint_as_float(h));
                }
            }
#pragma unroll
            for (int nb = 0; nb < 8; ++nb) {
                const int nc = wn * 64 + nb * 8 + gid;
                float b0 = Bs[cur][k0 + tig][nc];
                float b1 = Bs[cur][k0 + tig + 4][nc];
                unsigned bh[2], bl[2];
                bh[0] = f2tf32(b0); bl[0] = f2tf32(b0 - __uint_as_float(bh[0]));
                bh[1] = f2tf32(b1); bl[1] = f2tf32(b1 - __uint_as_float(bh[1]));
#pragma unroll
                for (int mb = 0; mb < 2; ++mb) mma_tf32(acc[mb][nb], ahi[mb], bh);
#pragma unroll
                for (int mb = 0; mb < 2; ++mb) mma_tf32(acc[mb][nb], ahi[mb], bl);
#pragma unroll
                for (int mb = 0; mb < 2; ++mb) mma_tf32(acc[mb][nb], alo[mb], bh);
            }
        }
        if (more) {
            CPA_WAIT0();
            __syncthreads();
        }
    }

#pragma unroll
    for (int mb = 0; mb < 2; ++mb) {
        const int row0 = m0 + wm * 32 + mb * 16 + gid;
#pragma unroll
        for (int nb = 0; nb < 8; ++nb) {
            const int col = n0 + wn * 64 + nb * 8 + tig * 2;
            float2 bv = *reinterpret_cast<const float2*>(bias + col);
            float2 v0 = make_float2(acc[mb][nb][0] + bv.x, acc[mb][nb][1] + bv.y);
            float2 v1 = make_float2(acc[mb][nb][2] + bv.x, acc[mb][nb][3] + bv.y);
            *reinterpret_cast<float2*>(C + (size_t)row0 * G4 + col)       = v0;
            *reinterpret_cast<float2*>(C + (size_t)(row0 + 8) * G4 + col) = v1;
        }
    }
}

// ---------------- persistent bidirectional LSTM: tensor-core recurrence ------------
// R16 shell (bid = dir*64+bt*8+nt, flag barrier, global h double buffer). The step
// z = h @ U now runs on tensor cores: warp w computes gate w's Z[16 x 32] via
// m16n8k8 tf32 MMAs, 3 terms (h_hi*U_hi + h_lo*U_hi + h_hi*U_lo) ~= fp32 accuracy.
// U_hi: tf32-rounded fp32 in smem [gate][unit][k] (k-stride 260, conflict-free
// fragment loads, no cvt at use). U_lo: bf16 pairs (k, k+4) packed per 32-bit word
// [gate][unit][pair] (unpack = 2 shifts). Gates recombine via smem z-exchange;
// state threads own fixed (row, 4 units), c register-resident.
// smem: Uh 133120 + Ul 67584 + hstage 16640 + zex 9216 = 226560 B (1 CTA/SM).
__global__ __launch_bounds__(128) void lstm_persist_k(
        const float* __restrict__ Uf, const float* __restrict__ Ub, int write_seq)
{
    extern __shared__ float smp[];
    float*    Uh  = smp;                                   // [4][32][260] tf32-as-f32
    unsigned* Ul  = reinterpret_cast<unsigned*>(smp + 33280); // [4][32][132] bf16 pairs
    float*    stg = smp + 50176;                           // h stage [16][260]
    float*    zex = smp + 54336;                           // [4][16][36]

    const int bid = blockIdx.x;
    const int dir = bid >> 6;
    const int bt  = (bid >> 3) & 7;
    const int nt  = bid & 7;
    const int grp = bid >> 3;
    const int tid = threadIdx.x;

    const float* U  = dir ? Ub : Uf;
    const float* Xw = dir ? g_XwB : g_XwF;
    float* hbuf = g_state + (size_t)dir * 2 * BB * HH;

    const unsigned base = *(volatile unsigned*)&g_flags[bid * 32];

    // ---- prep: split U slice into tf32-hi (f32) + bf16-lo pairs ----
    {
        const int g = tid >> 5, u = tid & 31;              // thread = (gate, unit)
        const float* Ucol = U + (size_t)g * HH + nt * 32 + u;
        float*    uh = Uh + (size_t)(g * 32 + u) * 260;
        unsigned* ul = Ul + (size_t)(g * 32 + u) * 132;
        for (int kb = 0; kb < 32; ++kb) {
            float lo8[8];
#pragma unroll
            for (int j = 0; j < 8; ++j) {
                float v = Ucol[(size_t)(kb * 8 + j) * G4];
                unsigned hb = f2tf32(v);
                uh[kb * 8 + j] = __uint_as_float(hb);
                lo8[j] = v - __uint_as_float(hb);
            }
#pragma unroll
            for (int tg = 0; tg < 4; ++tg) {
                unsigned w = (__float_as_uint(lo8[tg + 4]) & 0xffff0000u)
                           | (__float_as_uint(lo8[tg]) >> 16);
                ul[kb * 4 + tg] = w;
            }
        }
    }

    // zero my (bt, nt) patch of both h parity buffers
    for (int i = tid; i < 512; i += 128) {
        int r  = bt * 16 + (i >> 5);
        int cc = nt * 32 + (i & 31);
        __stcg(hbuf + (size_t)r * HH + cc, 0.f);
        __stcg(hbuf + (size_t)BB * HH + (size_t)r * HH + cc, 0.f);
    }

    grid_bar(bid, grp, base + 1);   // also orders Uh/Ul smem writes for all warps

    const int warp = tid >> 5;          // = gate
    const int lane = tid & 31;
    const int gid  = lane >> 2;         // 0..7
    const int tig  = lane & 3;          // 0..3
    const float*    uhw = Uh + (size_t)warp * 32 * 260;
    const unsigned* ulw = Ul + (size_t)warp * 32 * 132;

    // state-thread identity: row 0..15, 4-unit block 0..7
    const int srow = tid >> 3;
    const int sub  = tid & 7;
    const int r0   = bt * 16 + srow;
    const int ucol = nt * 32 + sub * 4;

    float4 cst = make_float4(0.f, 0.f, 0.f, 0.f);

    for (int s = 0; s < TT; ++s) {
        const int t   = dir ? (TT - 1 - s) : s;
        const int par = s & 1;
        const float* hRead  = hbuf + (size_t)par * BB * HH;
        float*       hWrite = hbuf + (size_t)(par ^ 1) * BB * HH;

        // Xw prefetch (state threads' 4 gates x 4 units; consumed after MMA)
        float4 xw[4];
        {
            const float* xwb = Xw + ((size_t)t * BB + r0) * G4 + ucol;
#pragma unroll
            for (int g = 0; g < 4; ++g)
                xw[g] = *reinterpret_cast<const float4*>(xwb + (size_t)g * HH);
        }

        // stage h tile (16 x 256)
#pragma unroll
        for (int i = 0; i < 8; ++i) {
            int f = tid + i * 128;
            int r = f >> 6, cq = f & 63;
            *reinterpret_cast<float4*>(&stg[r * 260 + cq * 4]) =
                __ldcg(reinterpret_cast<const float4*>(
                    hRead + (size_t)(bt * 16 + r) * HH + cq * 4));
        }
        __syncthreads();

        // ---- tensor-core k-loop: Z_gate[16 x 32] ----
        float c[4][4];
#pragma unroll
        for (int ut = 0; ut < 4; ++ut)
#pragma unroll
            for (int r = 0; r < 4; ++r) c[ut][r] = 0.f;

#pragma unroll 2
        for (int kb = 0; kb < 32; ++kb) {
            const int k0 = kb * 8;
            float v0 = stg[gid * 260 + k0 + tig];
            float v1 = stg[(gid + 8) * 260 + k0 + tig];
            float v2 = stg[gid * 260 + k0 + tig + 4];
            float v3 = stg[(gid + 8) * 260 + k0 + tig + 4];
            unsigned ahi[4] = {f2tf32(v0), f2tf32(v1), f2tf32(v2), f2tf32(v3)};
            unsigned alo[4] = {
                __float_as_uint(v0 - __uint_as_float(ahi[0])),
                __float_as_uint(v1 - __uint_as_float(ahi[1])),
                __float_as_uint(v2 - __uint_as_float(ahi[2])),
                __float_as_uint(v3 - __uint_as_float(ahi[3]))};
#pragma unroll
            for (int ut = 0; ut < 4; ++ut) {
                const float* bp = uhw + (size_t)(ut * 8 + gid) * 260 + k0 + tig;
                unsigned bh[2] = {__float_as_uint(bp[0]), __float_as_uint(bp[4])};
                unsigned w = ulw[(size_t)(ut * 8 + gid) * 132 + kb * 4 + tig];
                unsigned bl[2] = {w << 16, w & 0xffff0000u};
                mma_tf32(c[ut], ahi, bh);
                mma_tf32(c[ut], alo, bh);
                mma_tf32(c[ut], ahi, bl);
            }
        }

        // publish z to the gate exchange
#pragma unroll
        for (int ut = 0; ut < 4; ++ut) {
            float* zp = zex + (size_t)(warp * 16 + gid) * 36 + ut * 8 + tig * 2;
            *reinterpret_cast<float2*>(zp)          = make_float2(c[ut][0], c[ut][1]);
            *reinterpret_cast<float2*>(zp + 8 * 36) = make_float2(c[ut][2], c[ut][3]);
        }
        __syncthreads();

        // ---- state update: row srow, units ucol..+4 ----
        float4 zi = *reinterpret_cast<float4*>(&zex[(size_t)(0 * 16 + srow) * 36 + sub * 4]);
        float4 zf = *reinterpret_cast<float4*>(&zex[(size_t)(1 * 16 + srow) * 36 + sub * 4]);
        float4 zg = *reinterpret_cast<float4*>(&zex[(size_t)(2 * 16 + srow) * 36 + sub * 4]);
        float4 zo = *reinterpret_cast<float4*>(&zex[(size_t)(3 * 16 + srow) * 36 + sub * 4]);
        zi.x += xw[0].x; zi.y += xw[0].y; zi.z += xw[0].z; zi.w += xw[0].w;
        zf.x += xw[1].x; zf.y += xw[1].y; zf.z += xw[1].z; zf.w += xw[1].w;
        zg.x += xw[2].x; zg.y += xw[2].y; zg.z += xw[2].z; zg.w += xw[2].w;
        zo.x += xw[3].x; zo.y += xw[3].y; zo.z += xw[3].z; zo.w += xw[3].w;

        float4 hn;
        {
            float cc;
            cc = sigf(zf.x) * cst.x + sigf(zi.x) * tanhfast(zg.x);
            cst.x = cc; hn.x = sigf(zo.x) * tanhfast(cc);
            cc = sigf(zf.y) * cst.y + sigf(zi.y) * tanhfast(zg.y);
            cst.y = cc; hn.y = sigf(zo.y) * tanhfast(cc);
            cc = sigf(zf.z) * cst.z + sigf(zi.z) * tanhfast(zg.z);
            cst.z = cc; hn.z = sigf(zo.z) * tanhfast(cc);
            cc = sigf(zf.w) * cst.w + sigf(zi.w) * tanhfast(zg.w);
            cst.w = cc; hn.w = sigf(zo.w) * tanhfast(cc);
        }
        __stcg(reinterpret_cast<float4*>(hWrite + (size_t)r0 * HH + ucol), hn);
        if (write_seq)
            *reinterpret_cast<float4*>(
                g_seq + ((size_t)t * BB + r0) * (2 * HH) + dir * HH + ucol) = hn;

        grid_bar(bid, grp, base + (unsigned)s + 2);
    }
}

// ---------------- final dense + softmax ----------------
__global__ void final_k(const float* __restrict__ Wd, const float* __restrict__ bd,
                        float* __restrict__ out)
{
    int b = blockIdx.x, lane = threadIdx.x;
    const float* hf = g_state;                    // dir0 final h (parity buf0)
    const float* hb = g_state + 2 * BB * HH;      // dir1 final h (parity buf0)
    float acc[CC];
#pragma unroll
    for (int c = 0; c < CC; ++c) acc[c] = 0.f;
    for (int k = lane; k < 2 * HH; k += 32) {
        float hv = (k < HH) ? hf[(size_t)b * HH + k] : hb[(size_t)b * HH + k - HH];
        const float* w = Wd + (size_t)k * CC;
#pragma unroll
        for (int c = 0; c < CC; ++c) acc[c] = fmaf(hv, w[c], acc[c]);
    }
#pragma unroll
    for (int c = 0; c < CC; ++c)
#pragma unroll
        for (int o = 16; o; o >>= 1) acc[c] += __shfl_down_sync(0xffffffffu, acc[c], o);
    if (lane == 0) {
        float m = -1e30f;
#pragma unroll
        for (int c = 0; c < CC; ++c) { acc[c] += bd[c]; m = fmaxf(m, acc[c]); }
        float e[CC], s = 0.f;
#pragma unroll
        for (int c = 0; c < CC; ++c) { e[c] = expf(acc[c] - m); s += e[c]; }
        float inv = 1.f / s;
#pragma unroll
        for (int c = 0; c < CC; ++c) out[b * CC + c] = e[c] * inv;
    }
}

extern "C" void kernel_launch(void* const* d_in, const int* in_sizes, int n_in,
                              void* d_out, int out_size)
{
    const int*   x   = (const int*)  d_in[0];
    const float* emb = (const float*)d_in[1];
    const float* W1f = (const float*)d_in[2];
    const float* U1f = (const float*)d_in[3];
    const float* b1f = (const float*)d_in[4];
    const float* W1b = (const float*)d_in[5];
    const float* U1b = (const float*)d_in[6];
    const float* b1b = (const float*)d_in[7];
    const float* W2f = (const float*)d_in[8];
    const float* U2f = (const float*)d_in[9];
    const float* b2f = (const float*)d_in[10];
    const float* W2b = (const float*)d_in[11];
    const float* U2b = (const float*)d_in[12];
    const float* b2b = (const float*)d_in[13];
    const float* Wd  = (const float*)d_in[14];
    const float* bd  = (const float*)d_in[15];
    float* out = (float*)d_out;

    // Uh 133120 + Ul 67584 + hstage 16640 + zex 9216 = 226560
    const int LSTM_SMEM = 226560;

    static int smem_set = 0;
    if (!smem_set) {
        cudaFuncSetAttribute(lstm_persist_k,
                             cudaFuncAttributeMaxDynamicSharedMemorySize, LSTM_SMEM);
        smem_set = 1;
    }

    embed_k<<<(MROWS * 32) / 256, 256>>>(x, emb);

    dim3 gg(MROWS / 128, G4 / 128);

    // layer 1
    gemm_k<<<gg, 256>>>(0, 0, W1f, b1f, DD);
    gemm_k<<<gg, 256>>>(0, 1, W1b, b1b, DD);
    lstm_persist_k<<<NCTA, 128, LSTM_SMEM>>>(U1f, U1b, 1);

    // layer 2
    gemm_k<<<gg, 256>>>(1, 0, W2f, b2f, 2 * HH);
    gemm_k<<<gg, 256>>>(1, 1, W2b, b2b, 2 * HH);
    lstm_persist_k<<<NCTA, 128, LSTM_SMEM>>>(U2f, U2b, 0);

    final_k<<<BB, 32>>>(Wd, bd, out);
}